// round 16
// baseline (speedup 1.0000x reference)
#include <cuda_runtime.h>
#include <mma.h>
#include <math.h>
#include <stdint.h>

using namespace nvcuda;

#define NN 50000
#define EE 800000
#define IN_DIM 128
#define HID 128
#define OUT_DIM 40
#define KHOP 10
#define AH 64
#define ALPHA 0.1f
#define EPS 1e-5f

#define GB_BLOCKS 592            // <=4 blocks/SM on 148 SMs -> co-resident, spin-safe
#define GB_THREADS 256
#define SCAN_B 256
#define SCAN_NB ((NN + SCAN_B - 1) / SCAN_B)   // 196

#define PP_BLOCKS 1184           // 8 blocks/SM x 148 SMs -> co-resident persistent grid
#define PP_THREADS 256
#define PP_WARPS (PP_BLOCKS * (PP_THREADS / 32))   // 9472 warps

// ----------------------------------------------------------------------------
// Static device scratch
// ----------------------------------------------------------------------------
__device__ float g_xs[(KHOP + 1) * (size_t)NN * HID];   // 281.6 MB fp32 hops
__device__ float g_wsum[NN];
__device__ int   g_deg[NN];
__device__ int   g_rowptr[NN + 1];
__device__ int   g_cursor[NN];
__device__ int   g_bsum[SCAN_NB];
__device__ float2 g_edge[EE];                            // {src bits, enorm} CSR by dest

// software grid barrier state (counts self-reset; epochs reset by att_head tail)
__device__ int g_gb_count;
__device__ int g_gb_epoch;
__device__ int g_pp_count;
__device__ int g_pp_epoch;

// half weights (native [o][c] layouts -> col_major wmma B, no transpose needed)
__device__ __half g_W1h[HID * IN_DIM];        // [n][k]
__device__ __half g_W2h[HID * HID];           // [n][k]
__device__ __half g_attW1h[AH * 2 * HID];     // [o][c]  64 x 256
__device__ __half g_attW2h[16 * AH];          // [j][c]  16 x 64 (rows 11..15 = 0)
__device__ __half g_h1Wh[(HID / 2) * HID];    // [o][c]  64 x 128
__device__ __half g_h2Wh[48 * (HID / 2)];     // [j][c]  48 x 64 (rows 40..47 = 0)
__device__ float g_A1[HID], g_C1[HID], g_A2[HID], g_C2[HID], g_A3[HID / 2], g_C3[HID / 2];

// ----------------------------------------------------------------------------
// Software grid barriers
// ----------------------------------------------------------------------------
__device__ __forceinline__ void gb_barrier(int target) {
    __syncthreads();
    if (threadIdx.x == 0) {
        __threadfence();
        int old = atomicAdd(&g_gb_count, 1);
        if (old == GB_BLOCKS - 1) {
            g_gb_count = 0;
            __threadfence();
            atomicAdd(&g_gb_epoch, 1);
        }
        while (atomicAdd(&g_gb_epoch, 0) < target) { }
        __threadfence();
    }
    __syncthreads();
}

__device__ __forceinline__ void pp_barrier(int target) {
    __syncthreads();
    if (threadIdx.x == 0) {
        __threadfence();
        int old = atomicAdd(&g_pp_count, 1);
        if (old == PP_BLOCKS - 1) {
            g_pp_count = 0;
            __threadfence();
            atomicAdd(&g_pp_epoch, 1);
        }
        while (atomicAdd(&g_pp_epoch, 0) < target) { }
        __threadfence();
    }
    __syncthreads();
}

// ----------------------------------------------------------------------------
// graph_build: zero -> count -> scan -> fill, one kernel, 4 grid barriers
// ----------------------------------------------------------------------------
__global__ __launch_bounds__(GB_THREADS, 4) void graph_build_kernel(
        const int* __restrict__ ei, const float* __restrict__ ew) {
    __shared__ int sh[SCAN_B];
    __shared__ int blockOff;
    int t = threadIdx.x;
    int b = blockIdx.x;
    int gt = b * GB_THREADS + t;
    const int GSTRIDE = GB_BLOCKS * GB_THREADS;

    for (int i = gt; i < NN; i += GSTRIDE) {
        g_wsum[i] = 0.f; g_deg[i] = 0; g_cursor[i] = 0;
    }
    gb_barrier(1);

    for (int e = gt; e < EE; e += GSTRIDE) {
        int row = ei[e];
        int col = ei[EE + e];
        atomicAdd(&g_wsum[row], ew[e]);
        atomicAdd(&g_deg[col], 1);
    }
    gb_barrier(2);

    if (b < SCAN_NB) {
        int i = b * SCAN_B + t;
        sh[t] = (i < NN) ? g_deg[i] : 0;
        __syncthreads();
#pragma unroll
        for (int off = SCAN_B / 2; off > 0; off >>= 1) {
            if (t < off) sh[t] += sh[t + off];
            __syncthreads();
        }
        if (t == 0) g_bsum[b] = sh[0];
    }
    gb_barrier(3);

    if (b < SCAN_NB) {
        int part = 0;
        for (int j = t; j < b; j += SCAN_B) part += g_bsum[j];
        sh[t] = part;
        __syncthreads();
#pragma unroll
        for (int off = SCAN_B / 2; off > 0; off >>= 1) {
            if (t < off) sh[t] += sh[t + off];
            __syncthreads();
        }
        if (t == 0) blockOff = sh[0];
        __syncthreads();

        int i = b * SCAN_B + t;
        int v = (i < NN) ? g_deg[i] : 0;
        sh[t] = v;
        __syncthreads();
#pragma unroll
        for (int off = 1; off < SCAN_B; off <<= 1) {
            int x = (t >= off) ? sh[t - off] : 0;
            __syncthreads();
            sh[t] += x;
            __syncthreads();
        }
        if (i < NN) g_rowptr[i] = sh[t] - v + blockOff;
        if (i == NN - 1) g_rowptr[NN] = EE;
    }
    gb_barrier(4);

    for (int e = gt; e < EE; e += GSTRIDE) {
        int row = ei[e];
        int col = ei[EE + e];
        float en = ew[e] / fmaxf(g_wsum[row], 1.0f);
        int pos = g_rowptr[col] + atomicAdd(&g_cursor[col], 1);
        g_edge[pos] = make_float2(__int_as_float(row), en);
    }
}

// ----------------------------------------------------------------------------
// Prep: weight conversion + BN folding
// ----------------------------------------------------------------------------
__global__ void prep_kernel(const float* __restrict__ lin1_w, const float* __restrict__ lin1_b,
                            const float* __restrict__ bn1_g, const float* __restrict__ bn1_b,
                            const float* __restrict__ bn1_m, const float* __restrict__ bn1_v,
                            const float* __restrict__ lin2_w, const float* __restrict__ lin2_b,
                            const float* __restrict__ bn2_g, const float* __restrict__ bn2_b,
                            const float* __restrict__ bn2_m, const float* __restrict__ bn2_v,
                            const float* __restrict__ att1_w, const float* __restrict__ att2_w,
                            const float* __restrict__ head1_w, const float* __restrict__ head1_b,
                            const float* __restrict__ bn3_g, const float* __restrict__ bn3_b,
                            const float* __restrict__ bn3_m, const float* __restrict__ bn3_v,
                            const float* __restrict__ head2_w) {
    int tid = blockIdx.x * blockDim.x + threadIdx.x;
    if (tid < IN_DIM * HID) {
        g_W1h[tid] = __float2half(lin1_w[tid]);   // [n][k] native
        g_W2h[tid] = __float2half(lin2_w[tid]);
    }
    if (tid < AH * 2 * HID) g_attW1h[tid] = __float2half(att1_w[tid]);   // [o][c] native
    if (tid < 16 * AH) {
        int j = tid >> 6, c = tid & 63;
        g_attW2h[tid] = __float2half(j < KHOP + 1 ? att2_w[j * AH + c] : 0.f);
    }
    if (tid < (HID / 2) * HID) g_h1Wh[tid] = __float2half(head1_w[tid]); // [o][c] native
    if (tid < 48 * (HID / 2)) {
        int j = tid / 64;
        g_h2Wh[tid] = __float2half(j < OUT_DIM ? head2_w[tid] : 0.f);
    }
    if (tid < HID) {
        float a1 = bn1_g[tid] * rsqrtf(bn1_v[tid] + EPS);
        g_A1[tid] = a1;
        g_C1[tid] = lin1_b[tid] * a1 + bn1_b[tid] - bn1_m[tid] * a1;
        float a2 = bn2_g[tid] * rsqrtf(bn2_v[tid] + EPS);
        g_A2[tid] = a2;
        g_C2[tid] = lin2_b[tid] * a2 + bn2_b[tid] - bn2_m[tid] * a2;
    }
    if (tid < HID / 2) {
        float a3 = bn3_g[tid] * rsqrtf(bn3_v[tid] + EPS);
        g_A3[tid] = a3;
        g_C3[tid] = head1_b[tid] * a3 + bn3_b[tid] - bn3_m[tid] * a3;
    }
}

// ----------------------------------------------------------------------------
// Tensor-core fused stem (unchanged)
// ----------------------------------------------------------------------------
#define CS_LD 132
__global__ __launch_bounds__(256) void stem_kernel(const float* __restrict__ X) {
    extern __shared__ char smem[];
    __half (*Ah)[128]  = (__half(*)[128])(smem);
    __half (*H1h)[128] = (__half(*)[128])(smem + 16384);
    float  (*Cs)[CS_LD] = (float(*)[CS_LD])(smem + 32768);

    int tid = threadIdx.x;
    int m0 = blockIdx.x * 64;
    int wid = tid >> 5;
    int rowT = wid >> 1;
    int colT0 = (wid & 1) * 4;

    int r  = tid >> 2;
    int c0 = (tid & 3) * 32;
    int gm = m0 + r;

#pragma unroll
    for (int j = 0; j < 32; j += 4) {
        float4 v = make_float4(0.f, 0.f, 0.f, 0.f);
        if (gm < NN) v = *(const float4*)(X + (size_t)gm * 128 + c0 + j);
        Ah[r][c0 + j]     = __float2half(v.x);
        Ah[r][c0 + j + 1] = __float2half(v.y);
        Ah[r][c0 + j + 2] = __float2half(v.z);
        Ah[r][c0 + j + 3] = __float2half(v.w);
    }
    __syncthreads();

    wmma::fragment<wmma::accumulator, 16, 16, 16, float> cfr[4];
#pragma unroll
    for (int t = 0; t < 4; ++t) wmma::fill_fragment(cfr[t], 0.f);
#pragma unroll
    for (int kk = 0; kk < 8; ++kk) {
        wmma::fragment<wmma::matrix_a, 16, 16, 16, __half, wmma::row_major> afr;
        wmma::load_matrix_sync(afr, &Ah[rowT * 16][kk * 16], 128);
#pragma unroll
        for (int t = 0; t < 4; ++t) {
            wmma::fragment<wmma::matrix_b, 16, 16, 16, __half, wmma::col_major> bfr;
            wmma::load_matrix_sync(bfr, g_W1h + (colT0 + t) * 16 * 128 + kk * 16, 128);
            wmma::mma_sync(cfr[t], afr, bfr, cfr[t]);
        }
    }
#pragma unroll
    for (int t = 0; t < 4; ++t)
        wmma::store_matrix_sync(&Cs[rowT * 16][(colT0 + t) * 16], cfr[t], CS_LD, wmma::mem_row_major);
    __syncthreads();

    float h1v[32];
#pragma unroll
    for (int j = 0; j < 32; ++j) {
        int n = c0 + j;
        float v = fmaxf(Cs[r][n] * g_A1[n] + g_C1[n], 0.f);
        h1v[j] = v;
        H1h[r][n] = __float2half(v);
    }
    __syncthreads();

#pragma unroll
    for (int t = 0; t < 4; ++t) wmma::fill_fragment(cfr[t], 0.f);
#pragma unroll
    for (int kk = 0; kk < 8; ++kk) {
        wmma::fragment<wmma::matrix_a, 16, 16, 16, __half, wmma::row_major> afr;
        wmma::load_matrix_sync(afr, &H1h[rowT * 16][kk * 16], 128);
#pragma unroll
        for (int t = 0; t < 4; ++t) {
            wmma::fragment<wmma::matrix_b, 16, 16, 16, __half, wmma::col_major> bfr;
            wmma::load_matrix_sync(bfr, g_W2h + (colT0 + t) * 16 * 128 + kk * 16, 128);
            wmma::mma_sync(cfr[t], afr, bfr, cfr[t]);
        }
    }
#pragma unroll
    for (int t = 0; t < 4; ++t)
        wmma::store_matrix_sync(&Cs[rowT * 16][(colT0 + t) * 16], cfr[t], CS_LD, wmma::mem_row_major);
    __syncthreads();

    if (gm < NN) {
#pragma unroll
        for (int j = 0; j < 32; ++j) {
            int n = c0 + j;
            float v = fmaxf(Cs[r][n] * g_A2[n] + g_C2[n], 0.f) + h1v[j];
            g_xs[(size_t)gm * 128 + n] = v;
        }
    }
}
#define STEM_SMEM (16384 + 16384 + 64 * CS_LD * 4)

// ----------------------------------------------------------------------------
// PERSISTENT propagation: all 10 rounds in one launch. 1184 co-resident
// blocks, warp-per-node grid-stride (interleaved -> SM load variance ~1.4%),
// software grid barrier between rounds. Kills 9 launches + 10 wave tails.
// ----------------------------------------------------------------------------
__global__ __launch_bounds__(PP_THREADS, 8) void propagate_all_kernel() {
    const size_t layer = (size_t)NN * HID;
    int gw = (blockIdx.x * PP_THREADS + threadIdx.x) >> 5;   // global warp id
    int lane = threadIdx.x & 31;

    for (int k = 0; k < KHOP; ++k) {
        const float* __restrict__ hin = g_xs + (size_t)k * layer;
        float* __restrict__ hout = g_xs + (size_t)(k + 1) * layer;
        const float4* __restrict__ hin4 = (const float4*)hin;

        for (int node = gw; node < NN; node += PP_WARPS) {
            int s = g_rowptr[node];
            int e = g_rowptr[node + 1];

            float4 acc0 = make_float4(0.f, 0.f, 0.f, 0.f);
            float4 acc1 = make_float4(0.f, 0.f, 0.f, 0.f);

            int i = s;
            for (; i + 1 < e; i += 2) {
                float2 e0 = g_edge[i];
                float2 e1 = g_edge[i + 1];
                int s0 = __float_as_int(e0.x);
                int s1 = __float_as_int(e1.x);
                float4 v0 = __ldcg(&hin4[(size_t)s0 * 32 + lane]);
                float4 v1 = __ldcg(&hin4[(size_t)s1 * 32 + lane]);
                acc0.x += e0.y * v0.x; acc0.y += e0.y * v0.y; acc0.z += e0.y * v0.z; acc0.w += e0.y * v0.w;
                acc1.x += e1.y * v1.x; acc1.y += e1.y * v1.y; acc1.z += e1.y * v1.z; acc1.w += e1.y * v1.w;
            }
            if (i < e) {
                float2 e0 = g_edge[i];
                int s0 = __float_as_int(e0.x);
                float4 v0 = __ldcg(&hin4[(size_t)s0 * 32 + lane]);
                acc0.x += e0.y * v0.x; acc0.y += e0.y * v0.y; acc0.z += e0.y * v0.z; acc0.w += e0.y * v0.w;
            }
            float4 b = __ldcg(&((const float4*)g_xs)[(size_t)node * 32 + lane]);
            float4 o;
            o.x = (1.f - ALPHA) * (acc0.x + acc1.x) + ALPHA * b.x;
            o.y = (1.f - ALPHA) * (acc0.y + acc1.y) + ALPHA * b.y;
            o.z = (1.f - ALPHA) * (acc0.z + acc1.z) + ALPHA * b.z;
            o.w = (1.f - ALPHA) * (acc0.w + acc1.w) + ALPHA * b.w;
            ((float4*)hout)[(size_t)node * 32 + lane] = o;
        }
        if (k + 1 < KHOP) pp_barrier(k + 1);
    }
}

// ----------------------------------------------------------------------------
// wmma attention + hop fusion + head (resets both barrier epochs)
// ----------------------------------------------------------------------------
#define ATT_CS_LD 68
#define ATT_SMEM (32768 + 8192 + 16384 + 8192 + 64 * ATT_CS_LD * 4 + 4096)
__global__ __launch_bounds__(256) void att_head_kernel(const float* __restrict__ att1_b,
                                                       const float* __restrict__ att2_b,
                                                       const float* __restrict__ head2_b,
                                                       float* __restrict__ out) {
    extern __shared__ char sm[];
    __half (*CTXh)[256] = (__half(*)[256])(sm);
    __half (*A1h)[64]   = (__half(*)[64])(sm + 32768);
    __half (*FUSh)[128] = (__half(*)[128])(sm + 40960);
    __half (*Zh)[64]    = (__half(*)[64])(sm + 57344);
    float  (*Cs)[ATT_CS_LD] = (float(*)[ATT_CS_LD])(sm + 65536);
    float  (*WK)[16]    = (float(*)[16])(sm + 82944);

    if (blockIdx.x == 0 && threadIdx.x == 0) { g_gb_epoch = 0; g_pp_epoch = 0; }

    const size_t layer = (size_t)NN * HID;
    int tid = threadIdx.x;
    int wid = tid >> 5;
    int m0 = blockIdx.x * 64;
    int r  = tid >> 2;
    int c0 = (tid & 3) * 32;
    int gm = m0 + r;

    int tr0 = wid >> 2;
    int tr1 = tr0 + 2;
    int tcw = wid & 3;

    {
        const float* x0 = g_xs;
        const float* xK = g_xs + (size_t)KHOP * layer;
#pragma unroll
        for (int j = 0; j < 32; j += 4) {
            float4 v = make_float4(0.f, 0.f, 0.f, 0.f);
            float4 u = make_float4(0.f, 0.f, 0.f, 0.f);
            if (gm < NN) {
                v = *(const float4*)(x0 + (size_t)gm * 128 + c0 + j);
                u = *(const float4*)(xK + (size_t)gm * 128 + c0 + j);
            }
            CTXh[r][c0 + j]     = __float2half(v.x);
            CTXh[r][c0 + j + 1] = __float2half(v.y);
            CTXh[r][c0 + j + 2] = __float2half(v.z);
            CTXh[r][c0 + j + 3] = __float2half(v.w);
            CTXh[r][128 + c0 + j]     = __float2half(u.x);
            CTXh[r][128 + c0 + j + 1] = __float2half(u.y);
            CTXh[r][128 + c0 + j + 2] = __float2half(u.z);
            CTXh[r][128 + c0 + j + 3] = __float2half(u.w);
        }
    }
    __syncthreads();

    {
        wmma::fragment<wmma::accumulator, 16, 16, 16, float> acc0, acc1;
        wmma::fill_fragment(acc0, 0.f);
        wmma::fill_fragment(acc1, 0.f);
#pragma unroll
        for (int kk = 0; kk < 16; ++kk) {
            wmma::fragment<wmma::matrix_b, 16, 16, 16, __half, wmma::col_major> bfr;
            wmma::load_matrix_sync(bfr, g_attW1h + tcw * 16 * 256 + kk * 16, 256);
            wmma::fragment<wmma::matrix_a, 16, 16, 16, __half, wmma::row_major> afr;
            wmma::load_matrix_sync(afr, &CTXh[tr0 * 16][kk * 16], 256);
            wmma::mma_sync(acc0, afr, bfr, acc0);
            wmma::load_matrix_sync(afr, &CTXh[tr1 * 16][kk * 16], 256);
            wmma::mma_sync(acc1, afr, bfr, acc1);
        }
        wmma::store_matrix_sync(&Cs[tr0 * 16][tcw * 16], acc0, ATT_CS_LD, wmma::mem_row_major);
        wmma::store_matrix_sync(&Cs[tr1 * 16][tcw * 16], acc1, ATT_CS_LD, wmma::mem_row_major);
    }
    __syncthreads();

    {
        int cc = (tid & 3) * 16;
#pragma unroll
        for (int j = 0; j < 16; ++j) {
            int n = cc + j;
            float z = Cs[r][n] + att1_b[n];
            float g = 0.5f * z * (1.f + erff(z * 0.7071067811865475f));
            A1h[r][n] = __float2half(g);
        }
    }
    __syncthreads();

    if (wid < 4) {
        wmma::fragment<wmma::accumulator, 16, 16, 16, float> acc;
        wmma::fill_fragment(acc, 0.f);
#pragma unroll
        for (int kk = 0; kk < 4; ++kk) {
            wmma::fragment<wmma::matrix_a, 16, 16, 16, __half, wmma::row_major> afr;
            wmma::fragment<wmma::matrix_b, 16, 16, 16, __half, wmma::col_major> bfr;
            wmma::load_matrix_sync(afr, &A1h[wid * 16][kk * 16], 64);
            wmma::load_matrix_sync(bfr, g_attW2h + kk * 16, 64);
            wmma::mma_sync(acc, afr, bfr, acc);
        }
        wmma::store_matrix_sync(&Cs[wid * 16][0], acc, ATT_CS_LD, wmma::mem_row_major);
    }
    __syncthreads();

    if (tid < 64) {
        float lg[KHOP + 1];
        float m = -INFINITY;
#pragma unroll
        for (int j = 0; j <= KHOP; ++j) {
            lg[j] = Cs[tid][j] + att2_b[j];
            m = fmaxf(m, lg[j]);
        }
        float sum = 0.f;
#pragma unroll
        for (int j = 0; j <= KHOP; ++j) { lg[j] = expf(lg[j] - m); sum += lg[j]; }
        float inv = 1.f / sum;
#pragma unroll
        for (int j = 0; j <= KHOP; ++j) WK[tid][j] = lg[j] * inv;
    }
    __syncthreads();

    {
        float f[32];
#pragma unroll
        for (int j = 0; j < 32; ++j) f[j] = 0.f;
        if (gm < NN) {
#pragma unroll
            for (int k = 0; k <= KHOP; ++k) {
                float wkv = WK[r][k];
                const float4* src = (const float4*)(g_xs + (size_t)k * layer + (size_t)gm * 128 + c0);
#pragma unroll
                for (int j = 0; j < 8; ++j) {
                    float4 v = __ldcg(&src[j]);
                    f[j * 4]     += wkv * v.x;
                    f[j * 4 + 1] += wkv * v.y;
                    f[j * 4 + 2] += wkv * v.z;
                    f[j * 4 + 3] += wkv * v.w;
                }
            }
        }
#pragma unroll
        for (int j = 0; j < 32; ++j) FUSh[r][c0 + j] = __float2half(f[j]);
    }
    __syncthreads();

    {
        wmma::fragment<wmma::accumulator, 16, 16, 16, float> acc0, acc1;
        wmma::fill_fragment(acc0, 0.f);
        wmma::fill_fragment(acc1, 0.f);
#pragma unroll
        for (int kk = 0; kk < 8; ++kk) {
            wmma::fragment<wmma::matrix_b, 16, 16, 16, __half, wmma::col_major> bfr;
            wmma::load_matrix_sync(bfr, g_h1Wh + tcw * 16 * 128 + kk * 16, 128);
            wmma::fragment<wmma::matrix_a, 16, 16, 16, __half, wmma::row_major> afr;
            wmma::load_matrix_sync(afr, &FUSh[tr0 * 16][kk * 16], 128);
            wmma::mma_sync(acc0, afr, bfr, acc0);
            wmma::load_matrix_sync(afr, &FUSh[tr1 * 16][kk * 16], 128);
            wmma::mma_sync(acc1, afr, bfr, acc1);
        }
        wmma::store_matrix_sync(&Cs[tr0 * 16][tcw * 16], acc0, ATT_CS_LD, wmma::mem_row_major);
        wmma::store_matrix_sync(&Cs[tr1 * 16][tcw * 16], acc1, ATT_CS_LD, wmma::mem_row_major);
    }
    __syncthreads();

    {
        int cc = (tid & 3) * 16;
#pragma unroll
        for (int j = 0; j < 16; ++j) {
            int n = cc + j;
            float v = fmaxf(Cs[r][n] * g_A3[n] + g_C3[n], 0.f);
            Zh[r][n] = __float2half(v);
        }
    }
    __syncthreads();

    {
        for (int t = wid; t < 12; t += 8) {
            int tr = t / 3, tc = t % 3;
            wmma::fragment<wmma::accumulator, 16, 16, 16, float> acc;
            wmma::fill_fragment(acc, 0.f);
#pragma unroll
            for (int kk = 0; kk < 4; ++kk) {
                wmma::fragment<wmma::matrix_a, 16, 16, 16, __half, wmma::row_major> afr;
                wmma::fragment<wmma::matrix_b, 16, 16, 16, __half, wmma::col_major> bfr;
                wmma::load_matrix_sync(afr, &Zh[tr * 16][kk * 16], 64);
                wmma::load_matrix_sync(bfr, g_h2Wh + tc * 16 * 64 + kk * 16, 64);
                wmma::mma_sync(acc, afr, bfr, acc);
            }
            wmma::store_matrix_sync(&Cs[tr * 16][tc * 16], acc, ATT_CS_LD, wmma::mem_row_major);
        }
    }
    __syncthreads();

    for (int p = tid; p < 64 * OUT_DIM; p += 256) {
        int row = p / OUT_DIM, col = p % OUT_DIM;
        int node = m0 + row;
        if (node < NN) out[(size_t)node * OUT_DIM + col] = Cs[row][col] + head2_b[col];
    }
}

// ----------------------------------------------------------------------------
// Launch — graph_build(1), prep(2), stem(3), propagate_all(4 = ncu target), att_head(5)
// ----------------------------------------------------------------------------
extern "C" void kernel_launch(void* const* d_in, const int* in_sizes, int n_in,
                              void* d_out, int out_size) {
    const float* x       = (const float*)d_in[0];
    const int*   ei      = (const int*)d_in[1];      // int32 [2, E]
    const float* ew      = (const float*)d_in[2];
    const float* lin1_w  = (const float*)d_in[3];
    const float* lin1_b  = (const float*)d_in[4];
    const float* bn1_g   = (const float*)d_in[5];
    const float* bn1_b   = (const float*)d_in[6];
    const float* bn1_m   = (const float*)d_in[7];
    const float* bn1_v   = (const float*)d_in[8];
    const float* lin2_w  = (const float*)d_in[9];
    const float* lin2_b  = (const float*)d_in[10];
    const float* bn2_g   = (const float*)d_in[11];
    const float* bn2_b   = (const float*)d_in[12];
    const float* bn2_m   = (const float*)d_in[13];
    const float* bn2_v   = (const float*)d_in[14];
    const float* att1_w  = (const float*)d_in[15];
    const float* att1_b  = (const float*)d_in[16];
    const float* att2_w  = (const float*)d_in[17];
    const float* att2_b  = (const float*)d_in[18];
    const float* head1_w = (const float*)d_in[19];
    const float* head1_b = (const float*)d_in[20];
    const float* bn3_g   = (const float*)d_in[21];
    const float* bn3_b   = (const float*)d_in[22];
    const float* bn3_m   = (const float*)d_in[23];
    const float* bn3_v   = (const float*)d_in[24];
    const float* head2_w = (const float*)d_in[25];
    const float* head2_b = (const float*)d_in[26];
    float* out = (float*)d_out;

    cudaFuncSetAttribute(stem_kernel, cudaFuncAttributeMaxDynamicSharedMemorySize, STEM_SMEM);
    cudaFuncSetAttribute(att_head_kernel, cudaFuncAttributeMaxDynamicSharedMemorySize, ATT_SMEM);

    graph_build_kernel<<<GB_BLOCKS, GB_THREADS>>>(ei, ew);           // launch 1
    prep_kernel<<<(AH * 2 * HID + 255) / 256, 256>>>(                // launch 2
        lin1_w, lin1_b, bn1_g, bn1_b, bn1_m, bn1_v,
        lin2_w, lin2_b, bn2_g, bn2_b, bn2_m, bn2_v,
        att1_w, att2_w, head1_w, head1_b, bn3_g, bn3_b, bn3_m, bn3_v, head2_w);
    stem_kernel<<<(NN + 63) / 64, 256, STEM_SMEM>>>(x);              // launch 3

    propagate_all_kernel<<<PP_BLOCKS, PP_THREADS>>>();               // launch 4 (all 10 rounds)

    att_head_kernel<<<(NN + 63) / 64, 256, ATT_SMEM>>>(att1_b, att2_b, head2_b, out);
}

// round 17
// speedup vs baseline: 1.0657x; 1.0657x over previous
#include <cuda_runtime.h>
#include <mma.h>
#include <math.h>
#include <stdint.h>

using namespace nvcuda;

#define NN 50000
#define EE 800000
#define IN_DIM 128
#define HID 128
#define OUT_DIM 40
#define KHOP 10
#define AH 64
#define ALPHA 0.1f
#define EPS 1e-5f

#define GB_BLOCKS 592            // <=4 blocks/SM on 148 SMs -> co-resident, spin-safe
#define GB_THREADS 256
#define SCAN_B 256
#define SCAN_NB ((NN + SCAN_B - 1) / SCAN_B)   // 196

// ----------------------------------------------------------------------------
// Static device scratch
// ----------------------------------------------------------------------------
__device__ float g_xs[(KHOP + 1) * (size_t)NN * HID];   // 281.6 MB fp32 hops
__device__ float g_wsum[NN];
__device__ int   g_deg[NN];
__device__ int   g_rowptr[NN + 1];
__device__ int   g_cursor[NN];
__device__ int   g_bsum[SCAN_NB];
__device__ float2 g_edge[EE];                            // {src bits, enorm} CSR by dest

// software grid barrier state (count self-resets; epoch reset by att_head tail)
__device__ int g_gb_count;
__device__ int g_gb_epoch;

// half weights (native [o][c] layouts -> col_major wmma B, no transpose needed)
__device__ __half g_W1h[HID * IN_DIM];        // [n][k]
__device__ __half g_W2h[HID * HID];           // [n][k]
__device__ __half g_attW1h[AH * 2 * HID];     // [o][c]  64 x 256
__device__ __half g_attW2h[16 * AH];          // [j][c]  16 x 64 (rows 11..15 = 0)
__device__ __half g_h1Wh[(HID / 2) * HID];    // [o][c]  64 x 128
__device__ __half g_h2Wh[48 * (HID / 2)];     // [j][c]  48 x 64 (rows 40..47 = 0)
__device__ float g_A1[HID], g_C1[HID], g_A2[HID], g_C2[HID], g_A3[HID / 2], g_C3[HID / 2];

// ----------------------------------------------------------------------------
// Software grid barrier
// ----------------------------------------------------------------------------
__device__ __forceinline__ void gb_barrier(int target) {
    __syncthreads();
    if (threadIdx.x == 0) {
        __threadfence();
        int old = atomicAdd(&g_gb_count, 1);
        if (old == GB_BLOCKS - 1) {
            g_gb_count = 0;
            __threadfence();
            atomicAdd(&g_gb_epoch, 1);
        }
        while (atomicAdd(&g_gb_epoch, 0) < target) { }
        __threadfence();
    }
    __syncthreads();
}

// ----------------------------------------------------------------------------
// graph_build: zero -> count -> scan -> fill, one kernel, 4 grid barriers
// ----------------------------------------------------------------------------
__global__ __launch_bounds__(GB_THREADS, 4) void graph_build_kernel(
        const int* __restrict__ ei, const float* __restrict__ ew) {
    __shared__ int sh[SCAN_B];
    __shared__ int blockOff;
    int t = threadIdx.x;
    int b = blockIdx.x;
    int gt = b * GB_THREADS + t;
    const int GSTRIDE = GB_BLOCKS * GB_THREADS;

    for (int i = gt; i < NN; i += GSTRIDE) {
        g_wsum[i] = 0.f; g_deg[i] = 0; g_cursor[i] = 0;
    }
    gb_barrier(1);

    for (int e = gt; e < EE; e += GSTRIDE) {
        int row = ei[e];
        int col = ei[EE + e];
        atomicAdd(&g_wsum[row], ew[e]);
        atomicAdd(&g_deg[col], 1);
    }
    gb_barrier(2);

    if (b < SCAN_NB) {
        int i = b * SCAN_B + t;
        sh[t] = (i < NN) ? g_deg[i] : 0;
        __syncthreads();
#pragma unroll
        for (int off = SCAN_B / 2; off > 0; off >>= 1) {
            if (t < off) sh[t] += sh[t + off];
            __syncthreads();
        }
        if (t == 0) g_bsum[b] = sh[0];
    }
    gb_barrier(3);

    if (b < SCAN_NB) {
        int part = 0;
        for (int j = t; j < b; j += SCAN_B) part += g_bsum[j];
        sh[t] = part;
        __syncthreads();
#pragma unroll
        for (int off = SCAN_B / 2; off > 0; off >>= 1) {
            if (t < off) sh[t] += sh[t + off];
            __syncthreads();
        }
        if (t == 0) blockOff = sh[0];
        __syncthreads();

        int i = b * SCAN_B + t;
        int v = (i < NN) ? g_deg[i] : 0;
        sh[t] = v;
        __syncthreads();
#pragma unroll
        for (int off = 1; off < SCAN_B; off <<= 1) {
            int x = (t >= off) ? sh[t - off] : 0;
            __syncthreads();
            sh[t] += x;
            __syncthreads();
        }
        if (i < NN) g_rowptr[i] = sh[t] - v + blockOff;
        if (i == NN - 1) g_rowptr[NN] = EE;
    }
    gb_barrier(4);

    for (int e = gt; e < EE; e += GSTRIDE) {
        int row = ei[e];
        int col = ei[EE + e];
        float en = ew[e] / fmaxf(g_wsum[row], 1.0f);
        int pos = g_rowptr[col] + atomicAdd(&g_cursor[col], 1);
        g_edge[pos] = make_float2(__int_as_float(row), en);
    }
}

// ----------------------------------------------------------------------------
// Prep: weight conversion + BN folding
// ----------------------------------------------------------------------------
__global__ void prep_kernel(const float* __restrict__ lin1_w, const float* __restrict__ lin1_b,
                            const float* __restrict__ bn1_g, const float* __restrict__ bn1_b,
                            const float* __restrict__ bn1_m, const float* __restrict__ bn1_v,
                            const float* __restrict__ lin2_w, const float* __restrict__ lin2_b,
                            const float* __restrict__ bn2_g, const float* __restrict__ bn2_b,
                            const float* __restrict__ bn2_m, const float* __restrict__ bn2_v,
                            const float* __restrict__ att1_w, const float* __restrict__ att2_w,
                            const float* __restrict__ head1_w, const float* __restrict__ head1_b,
                            const float* __restrict__ bn3_g, const float* __restrict__ bn3_b,
                            const float* __restrict__ bn3_m, const float* __restrict__ bn3_v,
                            const float* __restrict__ head2_w) {
    int tid = blockIdx.x * blockDim.x + threadIdx.x;
    if (tid < IN_DIM * HID) {
        g_W1h[tid] = __float2half(lin1_w[tid]);   // [n][k] native
        g_W2h[tid] = __float2half(lin2_w[tid]);
    }
    if (tid < AH * 2 * HID) g_attW1h[tid] = __float2half(att1_w[tid]);   // [o][c] native
    if (tid < 16 * AH) {
        int j = tid >> 6, c = tid & 63;
        g_attW2h[tid] = __float2half(j < KHOP + 1 ? att2_w[j * AH + c] : 0.f);
    }
    if (tid < (HID / 2) * HID) g_h1Wh[tid] = __float2half(head1_w[tid]); // [o][c] native
    if (tid < 48 * (HID / 2)) {
        int j = tid / 64;
        g_h2Wh[tid] = __float2half(j < OUT_DIM ? head2_w[tid] : 0.f);
    }
    if (tid < HID) {
        float a1 = bn1_g[tid] * rsqrtf(bn1_v[tid] + EPS);
        g_A1[tid] = a1;
        g_C1[tid] = lin1_b[tid] * a1 + bn1_b[tid] - bn1_m[tid] * a1;
        float a2 = bn2_g[tid] * rsqrtf(bn2_v[tid] + EPS);
        g_A2[tid] = a2;
        g_C2[tid] = lin2_b[tid] * a2 + bn2_b[tid] - bn2_m[tid] * a2;
    }
    if (tid < HID / 2) {
        float a3 = bn3_g[tid] * rsqrtf(bn3_v[tid] + EPS);
        g_A3[tid] = a3;
        g_C3[tid] = head1_b[tid] * a3 + bn3_b[tid] - bn3_m[tid] * a3;
    }
}

// ----------------------------------------------------------------------------
// Tensor-core fused stem (unchanged)
// ----------------------------------------------------------------------------
#define CS_LD 132
__global__ __launch_bounds__(256) void stem_kernel(const float* __restrict__ X) {
    extern __shared__ char smem[];
    __half (*Ah)[128]  = (__half(*)[128])(smem);
    __half (*H1h)[128] = (__half(*)[128])(smem + 16384);
    float  (*Cs)[CS_LD] = (float(*)[CS_LD])(smem + 32768);

    int tid = threadIdx.x;
    int m0 = blockIdx.x * 64;
    int wid = tid >> 5;
    int rowT = wid >> 1;
    int colT0 = (wid & 1) * 4;

    int r  = tid >> 2;
    int c0 = (tid & 3) * 32;
    int gm = m0 + r;

#pragma unroll
    for (int j = 0; j < 32; j += 4) {
        float4 v = make_float4(0.f, 0.f, 0.f, 0.f);
        if (gm < NN) v = *(const float4*)(X + (size_t)gm * 128 + c0 + j);
        Ah[r][c0 + j]     = __float2half(v.x);
        Ah[r][c0 + j + 1] = __float2half(v.y);
        Ah[r][c0 + j + 2] = __float2half(v.z);
        Ah[r][c0 + j + 3] = __float2half(v.w);
    }
    __syncthreads();

    wmma::fragment<wmma::accumulator, 16, 16, 16, float> cfr[4];
#pragma unroll
    for (int t = 0; t < 4; ++t) wmma::fill_fragment(cfr[t], 0.f);
#pragma unroll
    for (int kk = 0; kk < 8; ++kk) {
        wmma::fragment<wmma::matrix_a, 16, 16, 16, __half, wmma::row_major> afr;
        wmma::load_matrix_sync(afr, &Ah[rowT * 16][kk * 16], 128);
#pragma unroll
        for (int t = 0; t < 4; ++t) {
            wmma::fragment<wmma::matrix_b, 16, 16, 16, __half, wmma::col_major> bfr;
            wmma::load_matrix_sync(bfr, g_W1h + (colT0 + t) * 16 * 128 + kk * 16, 128);
            wmma::mma_sync(cfr[t], afr, bfr, cfr[t]);
        }
    }
#pragma unroll
    for (int t = 0; t < 4; ++t)
        wmma::store_matrix_sync(&Cs[rowT * 16][(colT0 + t) * 16], cfr[t], CS_LD, wmma::mem_row_major);
    __syncthreads();

    float h1v[32];
#pragma unroll
    for (int j = 0; j < 32; ++j) {
        int n = c0 + j;
        float v = fmaxf(Cs[r][n] * g_A1[n] + g_C1[n], 0.f);
        h1v[j] = v;
        H1h[r][n] = __float2half(v);
    }
    __syncthreads();

#pragma unroll
    for (int t = 0; t < 4; ++t) wmma::fill_fragment(cfr[t], 0.f);
#pragma unroll
    for (int kk = 0; kk < 8; ++kk) {
        wmma::fragment<wmma::matrix_a, 16, 16, 16, __half, wmma::row_major> afr;
        wmma::load_matrix_sync(afr, &H1h[rowT * 16][kk * 16], 128);
#pragma unroll
        for (int t = 0; t < 4; ++t) {
            wmma::fragment<wmma::matrix_b, 16, 16, 16, __half, wmma::col_major> bfr;
            wmma::load_matrix_sync(bfr, g_W2h + (colT0 + t) * 16 * 128 + kk * 16, 128);
            wmma::mma_sync(cfr[t], afr, bfr, cfr[t]);
        }
    }
#pragma unroll
    for (int t = 0; t < 4; ++t)
        wmma::store_matrix_sync(&Cs[rowT * 16][(colT0 + t) * 16], cfr[t], CS_LD, wmma::mem_row_major);
    __syncthreads();

    if (gm < NN) {
#pragma unroll
        for (int j = 0; j < 32; ++j) {
            int n = c0 + j;
            float v = fmaxf(Cs[r][n] * g_A2[n] + g_C2[n], 0.f) + h1v[j];
            g_xs[(size_t)gm * 128 + n] = v;
        }
    }
}
#define STEM_SMEM (16384 + 16384 + 64 * CS_LD * 4)

// ----------------------------------------------------------------------------
// Propagation: R15 best — warp per node, unroll x2, __launch_bounds__(256,8)
// ----------------------------------------------------------------------------
__global__ __launch_bounds__(256, 8) void propagate_kernel(int k) {
    const size_t layer = (size_t)NN * HID;
    const float* __restrict__ hin = g_xs + (size_t)k * layer;
    float* __restrict__ hout = g_xs + (size_t)(k + 1) * layer;

    int gt = blockIdx.x * blockDim.x + threadIdx.x;
    int node = gt >> 5;
    int lane = gt & 31;
    if (node >= NN) return;
    int s = g_rowptr[node];
    int e = g_rowptr[node + 1];
    const float4* __restrict__ hin4 = (const float4*)hin;

    float4 acc0 = make_float4(0.f, 0.f, 0.f, 0.f);
    float4 acc1 = make_float4(0.f, 0.f, 0.f, 0.f);

    int i = s;
    for (; i + 1 < e; i += 2) {
        float2 e0 = g_edge[i];
        float2 e1 = g_edge[i + 1];
        int s0 = __float_as_int(e0.x);
        int s1 = __float_as_int(e1.x);
        float4 v0 = __ldcg(&hin4[(size_t)s0 * 32 + lane]);
        float4 v1 = __ldcg(&hin4[(size_t)s1 * 32 + lane]);
        acc0.x += e0.y * v0.x; acc0.y += e0.y * v0.y; acc0.z += e0.y * v0.z; acc0.w += e0.y * v0.w;
        acc1.x += e1.y * v1.x; acc1.y += e1.y * v1.y; acc1.z += e1.y * v1.z; acc1.w += e1.y * v1.w;
    }
    if (i < e) {
        float2 e0 = g_edge[i];
        int s0 = __float_as_int(e0.x);
        float4 v0 = __ldcg(&hin4[(size_t)s0 * 32 + lane]);
        acc0.x += e0.y * v0.x; acc0.y += e0.y * v0.y; acc0.z += e0.y * v0.z; acc0.w += e0.y * v0.w;
    }
    float4 b = __ldcg(&((const float4*)g_xs)[(size_t)node * 32 + lane]);
    float4 o;
    o.x = (1.f - ALPHA) * (acc0.x + acc1.x) + ALPHA * b.x;
    o.y = (1.f - ALPHA) * (acc0.y + acc1.y) + ALPHA * b.y;
    o.z = (1.f - ALPHA) * (acc0.z + acc1.z) + ALPHA * b.z;
    o.w = (1.f - ALPHA) * (acc0.w + acc1.w) + ALPHA * b.w;
    ((float4*)hout)[(size_t)node * 32 + lane] = o;
}

// ----------------------------------------------------------------------------
// wmma attention + hop fusion + head — smem regions ALIASED to cut footprint
// 87.3KB -> 57.9KB => 4 blocks/SM (was 2), 2x occupancy.
// Layout: [0..32K) CTXh, later reused as FUSh[0..16K) + Zh[16K..24K) + WK[24K..28K)
//         [32K..40K) A1h ; [40K..56.9K) Cs (LD=66)
// Phase order guarantees no aliasing hazard (syncs between all transitions).
// ----------------------------------------------------------------------------
#define ATT_CS_LD 66
#define ATT_SMEM (32768 + 8192 + 64 * ATT_CS_LD * 4)
__global__ __launch_bounds__(256) void att_head_kernel(const float* __restrict__ att1_b,
                                                       const float* __restrict__ att2_b,
                                                       const float* __restrict__ head2_b,
                                                       float* __restrict__ out) {
    extern __shared__ char sm[];
    __half (*CTXh)[256] = (__half(*)[256])(sm);                 // [0, 32K)
    __half (*FUSh)[128] = (__half(*)[128])(sm);                 // [0, 16K)  (CTXh dead)
    __half (*Zh)[64]    = (__half(*)[64])(sm + 16384);          // [16K, 24K)
    float  (*WK)[16]    = (float(*)[16])(sm + 24576);           // [24K, 28K)
    __half (*A1h)[64]   = (__half(*)[64])(sm + 32768);          // [32K, 40K)
    float  (*Cs)[ATT_CS_LD] = (float(*)[ATT_CS_LD])(sm + 40960);// [40K, 56.9K)

    if (blockIdx.x == 0 && threadIdx.x == 0) g_gb_epoch = 0;

    const size_t layer = (size_t)NN * HID;
    int tid = threadIdx.x;
    int wid = tid >> 5;
    int m0 = blockIdx.x * 64;
    int r  = tid >> 2;
    int c0 = (tid & 3) * 32;
    int gm = m0 + r;

    int tr0 = wid >> 2;
    int tr1 = tr0 + 2;
    int tcw = wid & 3;

    // phase 1: load ctx = [x0 | xK] as half
    {
        const float* x0 = g_xs;
        const float* xK = g_xs + (size_t)KHOP * layer;
#pragma unroll
        for (int j = 0; j < 32; j += 4) {
            float4 v = make_float4(0.f, 0.f, 0.f, 0.f);
            float4 u = make_float4(0.f, 0.f, 0.f, 0.f);
            if (gm < NN) {
                v = *(const float4*)(x0 + (size_t)gm * 128 + c0 + j);
                u = *(const float4*)(xK + (size_t)gm * 128 + c0 + j);
            }
            CTXh[r][c0 + j]     = __float2half(v.x);
            CTXh[r][c0 + j + 1] = __float2half(v.y);
            CTXh[r][c0 + j + 2] = __float2half(v.z);
            CTXh[r][c0 + j + 3] = __float2half(v.w);
            CTXh[r][128 + c0 + j]     = __float2half(u.x);
            CTXh[r][128 + c0 + j + 1] = __float2half(u.y);
            CTXh[r][128 + c0 + j + 2] = __float2half(u.z);
            CTXh[r][128 + c0 + j + 3] = __float2half(u.w);
        }
    }
    __syncthreads();

    // phase 2: att1 GEMM (CTXh last read here)
    {
        wmma::fragment<wmma::accumulator, 16, 16, 16, float> acc0, acc1;
        wmma::fill_fragment(acc0, 0.f);
        wmma::fill_fragment(acc1, 0.f);
#pragma unroll
        for (int kk = 0; kk < 16; ++kk) {
            wmma::fragment<wmma::matrix_b, 16, 16, 16, __half, wmma::col_major> bfr;
            wmma::load_matrix_sync(bfr, g_attW1h + tcw * 16 * 256 + kk * 16, 256);
            wmma::fragment<wmma::matrix_a, 16, 16, 16, __half, wmma::row_major> afr;
            wmma::load_matrix_sync(afr, &CTXh[tr0 * 16][kk * 16], 256);
            wmma::mma_sync(acc0, afr, bfr, acc0);
            wmma::load_matrix_sync(afr, &CTXh[tr1 * 16][kk * 16], 256);
            wmma::mma_sync(acc1, afr, bfr, acc1);
        }
        wmma::store_matrix_sync(&Cs[tr0 * 16][tcw * 16], acc0, ATT_CS_LD, wmma::mem_row_major);
        wmma::store_matrix_sync(&Cs[tr1 * 16][tcw * 16], acc1, ATT_CS_LD, wmma::mem_row_major);
    }
    __syncthreads();

    // phase 3: bias + gelu -> A1h
    {
        int cc = (tid & 3) * 16;
#pragma unroll
        for (int j = 0; j < 16; ++j) {
            int n = cc + j;
            float z = Cs[r][n] + att1_b[n];
            float g = 0.5f * z * (1.f + erff(z * 0.7071067811865475f));
            A1h[r][n] = __float2half(g);
        }
    }
    __syncthreads();

    // phase 4: att2 GEMM -> Cs[.][0..15]
    if (wid < 4) {
        wmma::fragment<wmma::accumulator, 16, 16, 16, float> acc;
        wmma::fill_fragment(acc, 0.f);
#pragma unroll
        for (int kk = 0; kk < 4; ++kk) {
            wmma::fragment<wmma::matrix_a, 16, 16, 16, __half, wmma::row_major> afr;
            wmma::fragment<wmma::matrix_b, 16, 16, 16, __half, wmma::col_major> bfr;
            wmma::load_matrix_sync(afr, &A1h[wid * 16][kk * 16], 64);
            wmma::load_matrix_sync(bfr, g_attW2h + kk * 16, 64);
            wmma::mma_sync(acc, afr, bfr, acc);
        }
        wmma::store_matrix_sync(&Cs[wid * 16][0], acc, ATT_CS_LD, wmma::mem_row_major);
    }
    __syncthreads();

    // phase 5: softmax -> WK (CTXh region reuse, disjoint from FUSh writes later)
    if (tid < 64) {
        float lg[KHOP + 1];
        float m = -INFINITY;
#pragma unroll
        for (int j = 0; j <= KHOP; ++j) {
            lg[j] = Cs[tid][j] + att2_b[j];
            m = fmaxf(m, lg[j]);
        }
        float sum = 0.f;
#pragma unroll
        for (int j = 0; j <= KHOP; ++j) { lg[j] = expf(lg[j] - m); sum += lg[j]; }
        float inv = 1.f / sum;
#pragma unroll
        for (int j = 0; j <= KHOP; ++j) WK[tid][j] = lg[j] * inv;
    }
    __syncthreads();

    // phase 6: hop fusion (streaming 11 layers) -> FUSh
    {
        float f[32];
#pragma unroll
        for (int j = 0; j < 32; ++j) f[j] = 0.f;
        if (gm < NN) {
#pragma unroll
            for (int k = 0; k <= KHOP; ++k) {
                float wkv = WK[r][k];
                const float4* src = (const float4*)(g_xs + (size_t)k * layer + (size_t)gm * 128 + c0);
#pragma unroll
                for (int j = 0; j < 8; ++j) {
                    float4 v = __ldcg(&src[j]);
                    f[j * 4]     += wkv * v.x;
                    f[j * 4 + 1] += wkv * v.y;
                    f[j * 4 + 2] += wkv * v.z;
                    f[j * 4 + 3] += wkv * v.w;
                }
            }
        }
#pragma unroll
        for (int j = 0; j < 32; ++j) FUSh[r][c0 + j] = __float2half(f[j]);
    }
    __syncthreads();

    // phase 7: head1 GEMM (FUSh last read)
    {
        wmma::fragment<wmma::accumulator, 16, 16, 16, float> acc0, acc1;
        wmma::fill_fragment(acc0, 0.f);
        wmma::fill_fragment(acc1, 0.f);
#pragma unroll
        for (int kk = 0; kk < 8; ++kk) {
            wmma::fragment<wmma::matrix_b, 16, 16, 16, __half, wmma::col_major> bfr;
            wmma::load_matrix_sync(bfr, g_h1Wh + tcw * 16 * 128 + kk * 16, 128);
            wmma::fragment<wmma::matrix_a, 16, 16, 16, __half, wmma::row_major> afr;
            wmma::load_matrix_sync(afr, &FUSh[tr0 * 16][kk * 16], 128);
            wmma::mma_sync(acc0, afr, bfr, acc0);
            wmma::load_matrix_sync(afr, &FUSh[tr1 * 16][kk * 16], 128);
            wmma::mma_sync(acc1, afr, bfr, acc1);
        }
        wmma::store_matrix_sync(&Cs[tr0 * 16][tcw * 16], acc0, ATT_CS_LD, wmma::mem_row_major);
        wmma::store_matrix_sync(&Cs[tr1 * 16][tcw * 16], acc1, ATT_CS_LD, wmma::mem_row_major);
    }
    __syncthreads();

    // phase 8: bn3 + relu -> Zh (FUSh dead)
    {
        int cc = (tid & 3) * 16;
#pragma unroll
        for (int j = 0; j < 16; ++j) {
            int n = cc + j;
            float v = fmaxf(Cs[r][n] * g_A3[n] + g_C3[n], 0.f);
            Zh[r][n] = __float2half(v);
        }
    }
    __syncthreads();

    // phase 9: head2 GEMM -> Cs 64x48
    {
        for (int t = wid; t < 12; t += 8) {
            int tr = t / 3, tc = t % 3;
            wmma::fragment<wmma::accumulator, 16, 16, 16, float> acc;
            wmma::fill_fragment(acc, 0.f);
#pragma unroll
            for (int kk = 0; kk < 4; ++kk) {
                wmma::fragment<wmma::matrix_a, 16, 16, 16, __half, wmma::row_major> afr;
                wmma::fragment<wmma::matrix_b, 16, 16, 16, __half, wmma::col_major> bfr;
                wmma::load_matrix_sync(afr, &Zh[tr * 16][kk * 16], 64);
                wmma::load_matrix_sync(bfr, g_h2Wh + tc * 16 * 64 + kk * 16, 64);
                wmma::mma_sync(acc, afr, bfr, acc);
            }
            wmma::store_matrix_sync(&Cs[tr * 16][tc * 16], acc, ATT_CS_LD, wmma::mem_row_major);
        }
    }
    __syncthreads();

    for (int p = tid; p < 64 * OUT_DIM; p += 256) {
        int row = p / OUT_DIM, col = p % OUT_DIM;
        int node = m0 + row;
        if (node < NN) out[(size_t)node * OUT_DIM + col] = Cs[row][col] + head2_b[col];
    }
}

// ----------------------------------------------------------------------------
// Launch — R15 structure (best known): gb(1), prep(2), stem(3), prop x10, att
// ----------------------------------------------------------------------------
extern "C" void kernel_launch(void* const* d_in, const int* in_sizes, int n_in,
                              void* d_out, int out_size) {
    const float* x       = (const float*)d_in[0];
    const int*   ei      = (const int*)d_in[1];      // int32 [2, E]
    const float* ew      = (const float*)d_in[2];
    const float* lin1_w  = (const float*)d_in[3];
    const float* lin1_b  = (const float*)d_in[4];
    const float* bn1_g   = (const float*)d_in[5];
    const float* bn1_b   = (const float*)d_in[6];
    const float* bn1_m   = (const float*)d_in[7];
    const float* bn1_v   = (const float*)d_in[8];
    const float* lin2_w  = (const float*)d_in[9];
    const float* lin2_b  = (const float*)d_in[10];
    const float* bn2_g   = (const float*)d_in[11];
    const float* bn2_b   = (const float*)d_in[12];
    const float* bn2_m   = (const float*)d_in[13];
    const float* bn2_v   = (const float*)d_in[14];
    const float* att1_w  = (const float*)d_in[15];
    const float* att1_b  = (const float*)d_in[16];
    const float* att2_w  = (const float*)d_in[17];
    const float* att2_b  = (const float*)d_in[18];
    const float* head1_w = (const float*)d_in[19];
    const float* head1_b = (const float*)d_in[20];
    const float* bn3_g   = (const float*)d_in[21];
    const float* bn3_b   = (const float*)d_in[22];
    const float* bn3_m   = (const float*)d_in[23];
    const float* bn3_v   = (const float*)d_in[24];
    const float* head2_w = (const float*)d_in[25];
    const float* head2_b = (const float*)d_in[26];
    float* out = (float*)d_out;

    cudaFuncSetAttribute(stem_kernel, cudaFuncAttributeMaxDynamicSharedMemorySize, STEM_SMEM);
    cudaFuncSetAttribute(att_head_kernel, cudaFuncAttributeMaxDynamicSharedMemorySize, ATT_SMEM);

    graph_build_kernel<<<GB_BLOCKS, GB_THREADS>>>(ei, ew);           // launch 1
    prep_kernel<<<(AH * 2 * HID + 255) / 256, 256>>>(                // launch 2
        lin1_w, lin1_b, bn1_g, bn1_b, bn1_m, bn1_v,
        lin2_w, lin2_b, bn2_g, bn2_b, bn2_m, bn2_v,
        att1_w, att2_w, head1_w, head1_b, bn3_g, bn3_b, bn3_m, bn3_v, head2_w);
    stem_kernel<<<(NN + 63) / 64, 256, STEM_SMEM>>>(x);              // launch 3

    for (int k = 0; k < KHOP; ++k) {                                 // launch 4 = propagate(k=0)
        propagate_kernel<<<(NN * 32 + 255) / 256, 256>>>(k);
    }

    att_head_kernel<<<(NN + 63) / 64, 256, ATT_SMEM>>>(att1_b, att2_b, head2_b, out);
}